// round 16
// baseline (speedup 1.0000x reference)
#include <cuda_runtime.h>
#include <math.h>

typedef unsigned long long u64;

__device__ __forceinline__ void ffma2(u64 &d, u64 a, u64 b) {
    asm("fma.rn.f32x2 %0, %1, %2, %0;" : "+l"(d) : "l"(a), "l"(b));
}
__device__ __forceinline__ u64 pack2(float lo, float hi) {
    u64 r; asm("mov.b64 %0, {%1, %2};" : "=l"(r) : "f"(lo), "f"(hi)); return r;
}
__device__ __forceinline__ void unpack2(u64 v, float &lo, float &hi) {
    asm("mov.b64 {%0, %1}, %2;" : "=f"(lo), "=f"(hi) : "l"(v));
}

// B-tile pair swizzle: logical float-pair p -> p ^ ((p>>4)&3).
// Read addresses (p = 4*tx + c) become bank-conflict-free (verified: all 16
// LDS.64 addresses hit distinct bank pairs).
__device__ __forceinline__ void storeB_sw(float* Bs_row, int bc, float4 v) {
    int p  = bc >> 1;              // even logical pair index
    int g  = (p >> 4) & 3;
    int q0 = p ^ g;
    int base = (q0 & ~1) * 2;      // 16B-aligned block holding both pairs
    float4 w = (g & 1) ? make_float4(v.z, v.w, v.x, v.y) : v;
    *(float4*)(Bs_row + base) = w;
}
__device__ __forceinline__ u64 loadB_sw(const float* Bs_row, int tx, int c) {
    int p  = tx * 4 + c;
    int pp = p ^ (tx >> 2);
    return *(const u64*)(Bs_row + pp * 2);
}

#define BHX 32
#define SEQ 2048
#define HD  64
#define FEAT_ELEMS (BHX*SEQ*HD)

__device__ __align__(128) float g_qf[FEAT_ELEMS];
__device__ __align__(128) float g_kf[FEAT_ELEMS];
__device__ __align__(128) float g_rq[FEAT_ELEMS];
__device__ __align__(128) float g_rk[FEAT_ELEMS];
__device__ __align__(128) float g_v [FEAT_ELEMS];
__device__ __align__(128) float g_ao[FEAT_ELEMS];

// ---------------------------------------------------------------------------
// Kernel 1: QKV GEMM + bias + elu+1 + RoPE. R5 structure + swizzled B tile.
// ---------------------------------------------------------------------------
__global__ __launch_bounds__(256) void qkv_gemm(const float* __restrict__ X,
                                                const float* __restrict__ W,
                                                const float* __restrict__ bias) {
    __shared__ __align__(16) float As[16][132];
    __shared__ __align__(16) float Bs[16][128];
    const int tid = threadIdx.x;
    const int bm = blockIdx.y * 128;
    const int bn = blockIdx.x * 128;
    const int tx = tid & 15, ty = tid >> 4;
    const int ar = tid >> 2,  ac = (tid & 3) * 4;
    const int br = tid >> 5,  bc = (tid & 31) * 4;

    u64 acc2[8][4];
    #pragma unroll
    for (int i = 0; i < 8; i++)
        #pragma unroll
        for (int p = 0; p < 4; p++) acc2[i][p] = 0ull;

    for (int kt = 0; kt < 1024; kt += 16) {
        #pragma unroll
        for (int l = 0; l < 2; l++) {
            int r = ar + l * 64;
            float4 v = *(const float4*)(X + (size_t)(bm + r) * 1024 + kt + ac);
            As[ac+0][r] = v.x; As[ac+1][r] = v.y; As[ac+2][r] = v.z; As[ac+3][r] = v.w;
        }
        #pragma unroll
        for (int l = 0; l < 2; l++) {
            int r = br + l * 8;
            float4 v = *(const float4*)(W + (size_t)(kt + r) * 3072 + bn + bc);
            storeB_sw(&Bs[r][0], bc, v);
        }
        __syncthreads();
        #pragma unroll
        for (int k = 0; k < 16; k++) {
            float af[8];
            *(float4*)(af)     = *(const float4*)(&As[k][ty*8]);
            *(float4*)(af + 4) = *(const float4*)(&As[k][ty*8 + 4]);
            u64 b0 = loadB_sw(&Bs[k][0], tx, 0);
            u64 b1 = loadB_sw(&Bs[k][0], tx, 1);
            u64 b2 = loadB_sw(&Bs[k][0], tx, 2);
            u64 b3 = loadB_sw(&Bs[k][0], tx, 3);
            #pragma unroll
            for (int i = 0; i < 8; i++) {
                u64 ap = pack2(af[i], af[i]);
                ffma2(acc2[i][0], ap, b0);
                ffma2(acc2[i][1], ap, b1);
                ffma2(acc2[i][2], ap, b2);
                ffma2(acc2[i][3], ap, b3);
            }
        }
        __syncthreads();
    }

    const int col_base = bn + tx * 8;
    const int which = col_base >> 10;
    float theta[4];
    if (which != 2) {
        #pragma unroll
        for (int p = 0; p < 4; p++) {
            int pi = ((col_base & 63) + 2*p) >> 1;
            theta[p] = (float)(1.0 / pow(10000.0, (double)pi * (1.0 / 32.0)));
        }
    }
    #pragma unroll
    for (int i = 0; i < 8; i++) {
        int r = bm + ty * 8 + i;
        int b = r >> 11, n = r & 2047;
        #pragma unroll
        for (int p = 0; p < 4; p++) {
            int col0 = col_base + 2 * p;
            int d0 = col0 & 1023;
            int h = d0 >> 6, e0 = d0 & 63;
            int idx0 = ((b * 16 + h) * 2048 + n) * 64 + e0;
            float a0, a1;
            unpack2(acc2[i][p], a0, a1);
            float v0 = a0 + bias[col0];
            float v1 = a1 + bias[col0 + 1];
            if (which == 2) {
                g_v[idx0]     = v0;
                g_v[idx0 + 1] = v1;
            } else {
                float f0 = (v0 > 0.f) ? (v0 + 1.f) : expf(v0);
                float f1 = (v1 > 0.f) ? (v1 + 1.f) : expf(v1);
                float s, c;
                sincosf((float)n * theta[p], &s, &c);
                float r0 = f0 * c - f1 * s;
                float r1 = f0 * s + f1 * c;
                if (which == 0) {
                    g_qf[idx0] = f0; g_qf[idx0 + 1] = f1;
                    g_rq[idx0] = r0; g_rq[idx0 + 1] = r1;
                } else {
                    g_kf[idx0] = f0; g_kf[idx0 + 1] = f1;
                    g_rk[idx0] = r0; g_rk[idx0 + 1] = r1;
                }
            }
        }
    }
}

// ---------------------------------------------------------------------------
// Kernel 2: fused attention (R11 measured config — unchanged).
// ---------------------------------------------------------------------------
#define ST_QP 130
#define ST_KP 66
#define ST_W  130
#define ST_V  68

__global__ __launch_bounds__(256) void attn_kernel() {
    extern __shared__ char smraw[];
    float2* qp  = (float2*)smraw;                   // 66560 B
    float2* kp  = (float2*)(smraw + 66560);         // 33792 B
    float*  w_s = (float*)(smraw + 66560);          // alias kp
    float*  v_s = (float*)(smraw + 100352);         // 17408 B
    const int tid = threadIdx.x;
    const int tx = tid & 15, ty = tid >> 4;
    const int bh = blockIdx.y;
    const int q0 = blockIdx.x * 128;
    const size_t qbase = (size_t)(bh * 2048 + q0) * 64;
    const size_t kbase0 = (size_t)(bh * 2048) * 64;

    #pragma unroll
    for (int l = 0; l < 8; l++) {
        int t = tid + l * 256;
        int row = t >> 4, c4 = (t & 15) * 4;
        float4 a = *(const float4*)(g_rq + qbase + row * 64 + c4);
        float4 b = *(const float4*)(g_qf + qbase + row * 64 + c4);
        qp[(c4+0)*ST_QP + row] = make_float2(a.x, b.x);
        qp[(c4+1)*ST_QP + row] = make_float2(a.y, b.y);
        qp[(c4+2)*ST_QP + row] = make_float2(a.z, b.z);
        qp[(c4+3)*ST_QP + row] = make_float2(a.w, b.w);
    }

    u64 out2[4][4];
    #pragma unroll
    for (int p = 0; p < 4; p++)
        #pragma unroll
        for (int c = 0; c < 4; c++) out2[p][c] = 0ull;

    __syncthreads();

    for (int kt = 0; kt < 32; kt++) {
        const size_t kb = kbase0 + (size_t)kt * 64 * 64;
        #pragma unroll
        for (int l = 0; l < 4; l++) {
            int t = tid + l * 256;
            int row = t >> 4, c4 = (t & 15) * 4;
            float4 a = *(const float4*)(g_rk + kb + row * 64 + c4);
            float4 b = *(const float4*)(g_kf + kb + row * 64 + c4);
            kp[(c4+0)*ST_KP + row] = make_float2(a.x, b.x);
            kp[(c4+1)*ST_KP + row] = make_float2(a.y, b.y);
            kp[(c4+2)*ST_KP + row] = make_float2(a.z, b.z);
            kp[(c4+3)*ST_KP + row] = make_float2(a.w, b.w);
            *(float4*)(v_s + row * ST_V + c4) = *(const float4*)(g_v + kb + row * 64 + c4);
        }
        __syncthreads();

        u64 acc2[8][4];
        #pragma unroll
        for (int i = 0; i < 8; i++)
            #pragma unroll
            for (int c = 0; c < 4; c++) acc2[i][c] = 0ull;
        #pragma unroll 4
        for (int k = 0; k < 64; k++) {
            u64 a[8], b[4];
            #pragma unroll
            for (int rr = 0; rr < 8; rr++)
                a[rr] = *(const u64*)(qp + k*ST_QP + ty*8 + rr);
            #pragma unroll
            for (int c = 0; c < 4; c++)
                b[c] = *(const u64*)(kp + k*ST_KP + tx + 16*c);
            #pragma unroll
            for (int rr = 0; rr < 8; rr++)
                #pragma unroll
                for (int c = 0; c < 4; c++)
                    ffma2(acc2[rr][c], a[rr], b[c]);
        }
        __syncthreads();

        #pragma unroll
        for (int c = 0; c < 4; c++)
            #pragma unroll
            for (int p = 0; p < 4; p++) {
                float n0, d0, n1, d1;
                unpack2(acc2[2*p][c],   n0, d0);
                unpack2(acc2[2*p+1][c], n1, d1);
                u64 wpair = pack2(__fdividef(n0, d0), __fdividef(n1, d1));
                *(u64*)(w_s + (tx + 16*c) * ST_W + ty*8 + 2*p) = wpair;
            }
        __syncthreads();

        #pragma unroll 4
        for (int j = 0; j < 64; j++) {
            u64 wp[4];
            #pragma unroll
            for (int p = 0; p < 4; p++)
                wp[p] = *(const u64*)(w_s + j*ST_W + ty*8 + 2*p);
            u64 vp[4];
            #pragma unroll
            for (int ce = 0; ce < 4; ce++) {
                float vv = v_s[j*ST_V + tx + 16*ce];
                vp[ce] = pack2(vv, vv);
            }
            #pragma unroll
            for (int p = 0; p < 4; p++)
                #pragma unroll
                for (int ce = 0; ce < 4; ce++)
                    ffma2(out2[p][ce], wp[p], vp[ce]);
        }
        __syncthreads();
    }

    float* og = g_ao + qbase;
    #pragma unroll
    for (int p = 0; p < 4; p++)
        #pragma unroll
        for (int ce = 0; ce < 4; ce++) {
            float lo, hi;
            unpack2(out2[p][ce], lo, hi);
            int e = tx + 16*ce;
            og[(ty*8 + 2*p)     * 64 + e] = lo;
            og[(ty*8 + 2*p + 1) * 64 + e] = hi;
        }
}

// ---------------------------------------------------------------------------
// Kernel 3: output projection. R5 structure + swizzled B tile.
// ---------------------------------------------------------------------------
__global__ __launch_bounds__(256) void proj_gemm(const float* __restrict__ W,
                                                 const float* __restrict__ bias,
                                                 float* __restrict__ out) {
    __shared__ __align__(16) float As[16][132];
    __shared__ __align__(16) float Bs[16][128];
    const int tid = threadIdx.x;
    const int bm = blockIdx.y * 128;
    const int bn = blockIdx.x * 128;
    const int tx = tid & 15, ty = tid >> 4;
    const int ar = tid >> 2,  ac = (tid & 3) * 4;
    const int br = tid >> 5,  bc = (tid & 31) * 4;

    u64 acc2[8][4];
    #pragma unroll
    for (int i = 0; i < 8; i++)
        #pragma unroll
        for (int p = 0; p < 4; p++) acc2[i][p] = 0ull;

    for (int kt = 0; kt < 1024; kt += 16) {
        #pragma unroll
        for (int l = 0; l < 2; l++) {
            int r = bm + ar + l * 64;
            int d = kt + ac;
            int b = r >> 11, n = r & 2047;
            int h = d >> 6,  e = d & 63;
            float4 v = *(const float4*)(g_ao + (size_t)((b * 16 + h) * 2048 + n) * 64 + e);
            int rr = ar + l * 64;
            As[ac+0][rr] = v.x; As[ac+1][rr] = v.y; As[ac+2][rr] = v.z; As[ac+3][rr] = v.w;
        }
        #pragma unroll
        for (int l = 0; l < 2; l++) {
            int r = br + l * 8;
            float4 v = *(const float4*)(W + (size_t)(kt + r) * 1024 + bn + bc);
            storeB_sw(&Bs[r][0], bc, v);
        }
        __syncthreads();
        #pragma unroll
        for (int k = 0; k < 16; k++) {
            float af[8];
            *(float4*)(af)     = *(const float4*)(&As[k][ty*8]);
            *(float4*)(af + 4) = *(const float4*)(&As[k][ty*8 + 4]);
            u64 b0 = loadB_sw(&Bs[k][0], tx, 0);
            u64 b1 = loadB_sw(&Bs[k][0], tx, 1);
            u64 b2 = loadB_sw(&Bs[k][0], tx, 2);
            u64 b3 = loadB_sw(&Bs[k][0], tx, 3);
            #pragma unroll
            for (int i = 0; i < 8; i++) {
                u64 ap = pack2(af[i], af[i]);
                ffma2(acc2[i][0], ap, b0);
                ffma2(acc2[i][1], ap, b1);
                ffma2(acc2[i][2], ap, b2);
                ffma2(acc2[i][3], ap, b3);
            }
        }
        __syncthreads();
    }

    #pragma unroll
    for (int i = 0; i < 8; i++) {
        int r = bm + ty * 8 + i;
        #pragma unroll
        for (int p = 0; p < 4; p++) {
            int col0 = bn + tx * 8 + 2*p;
            float a0, a1;
            unpack2(acc2[i][p], a0, a1);
            *(float2*)(out + (size_t)r * 1024 + col0) =
                make_float2(a0 + bias[col0], a1 + bias[col0 + 1]);
        }
    }
}

// ---------------------------------------------------------------------------
extern "C" void kernel_launch(void* const* d_in, const int* in_sizes, int n_in,
                              void* d_out, int out_size) {
    const float* x     = (const float*)d_in[0];
    const float* w_qkv = (const float*)d_in[1];
    const float* b_qkv = (const float*)d_in[2];
    const float* w_out = (const float*)d_in[3];
    const float* b_out = (const float*)d_in[4];
    float* out = (float*)d_out;

    const int ATTN_SMEM = 117760;
    cudaFuncSetAttribute(attn_kernel, cudaFuncAttributeMaxDynamicSharedMemorySize, ATTN_SMEM);

    qkv_gemm<<<dim3(24, 32), 256>>>(x, w_qkv, b_qkv);
    attn_kernel<<<dim3(16, 32), 256, ATTN_SMEM>>>();
    proj_gemm<<<dim3(8, 32), 256>>>(w_out, b_out, out);
}